// round 1
// baseline (speedup 1.0000x reference)
#include <cuda_runtime.h>
#include <math.h>

#define FULLMASK 0xffffffffu

constexpr int Bb = 8;
constexpr int Nn = 7168;
constexpr int Uu = 49152;
constexpr int Cc = 64;

// scratch: post-LN1 attention output
__device__ float g_z1[Bb * Nn * Cc];

__device__ __forceinline__ float warp_sum(float v) {
#pragma unroll
    for (int off = 16; off; off >>= 1) v += __shfl_xor_sync(FULLMASK, v, off);
    return v;
}

// ---------------------------------------------------------------------------
// Kernel A: bunch attention (warp per x-token) + LN1 -> g_z1
// ---------------------------------------------------------------------------
template <int TO>
__device__ __forceinline__ void attn_body(
    const float* __restrict__ u, const float* __restrict__ x,
    const float* sWq, const float* sWkT, const float* sWv,
    const float* sbq, const float* sbk, const float* sbv,
    const float* sg1, const float* sbe1,
    float* myLog, int b, int n, int l)
{
    int t, S0, S1;
    if (TO == 4)      { t = n;        S0 = 0;     S1 = 24576; }
    else if (TO == 8) { t = n - 4096; S0 = 8192;  S1 = 32768; }
    else              { t = n - 6144; S0 = 16384; S1 = 40960; }
    int cidx = t * TO;
    int base = (cidx < 8192) ? (S0 + cidx) : (S1 + cidx - 8192);
    const float* uptr = u + ((size_t)b * Uu + base) * Cc;
    const float* xptr = x + ((size_t)b * Nn + n) * Cc;

    float xv0 = xptr[l], xv1 = xptr[l + 32];

    // q[out] = bq + x @ Wq, then fold in attention scale 1/8
    float q0 = sbq[l], q1 = sbq[l + 32];
#pragma unroll
    for (int in = 0; in < 32; in++) {
        float xb = __shfl_sync(FULLMASK, xv0, in);
        q0 += xb * sWq[in * 64 + l];
        q1 += xb * sWq[in * 64 + l + 32];
    }
#pragma unroll
    for (int in = 0; in < 32; in++) {
        float xb = __shfl_sync(FULLMASK, xv1, in);
        q0 += xb * sWq[(in + 32) * 64 + l];
        q1 += xb * sWq[(in + 32) * 64 + l + 32];
    }
    q0 *= 0.125f;
    q1 *= 0.125f;

    // w[g][in] = sum_{oc in group g} Wk[in][oc] * q[oc]   (and bk·q per group)
    float w0[4] = {0.f, 0.f, 0.f, 0.f}, w1[4] = {0.f, 0.f, 0.f, 0.f};
    float bkq[4] = {0.f, 0.f, 0.f, 0.f};
#pragma unroll
    for (int oc = 0; oc < 32; oc++) {
        float qb = __shfl_sync(FULLMASK, q0, oc);
        const int g = oc >> 4;
        w0[g] += qb * sWkT[oc * 65 + l];
        w1[g] += qb * sWkT[oc * 65 + l + 32];
        bkq[g] += qb * sbk[oc];
    }
#pragma unroll
    for (int oc = 32; oc < 64; oc++) {
        float qb = __shfl_sync(FULLMASK, q1, oc - 32);
        const int g = oc >> 4;
        w0[g] += qb * sWkT[oc * 65 + l];
        w1[g] += qb * sWkT[oc * 65 + l + 32];
        bkq[g] += qb * sbk[oc];
    }

    // load the TO contiguous u rows into registers
    float ur0[TO], ur1[TO];
#pragma unroll
    for (int r = 0; r < TO; r++) {
        ur0[r] = uptr[r * 64 + l];
        ur1[r] = uptr[r * 64 + l + 32];
    }

    // logits
#pragma unroll
    for (int r = 0; r < TO; r++) {
        float p0 = ur0[r] * w0[0] + ur1[r] * w1[0];
        float p1 = ur0[r] * w0[1] + ur1[r] * w1[1];
        float p2 = ur0[r] * w0[2] + ur1[r] * w1[2];
        float p3 = ur0[r] * w0[3] + ur1[r] * w1[3];
#pragma unroll
        for (int off = 16; off; off >>= 1) {
            p0 += __shfl_xor_sync(FULLMASK, p0, off);
            p1 += __shfl_xor_sync(FULLMASK, p1, off);
            p2 += __shfl_xor_sync(FULLMASK, p2, off);
            p3 += __shfl_xor_sync(FULLMASK, p3, off);
        }
        if (l == 0) {
            myLog[r * 4 + 0] = p0 + bkq[0];
            myLog[r * 4 + 1] = p1 + bkq[1];
            myLog[r * 4 + 2] = p2 + bkq[2];
            myLog[r * 4 + 3] = p3 + bkq[3];
        }
    }
    __syncwarp();

    // softmax over r, one group per lane (lanes 0..3)
    if (l < 4) {
        float m = -1e30f;
#pragma unroll
        for (int r = 0; r < TO; r++) m = fmaxf(m, myLog[r * 4 + l]);
        float s = 0.f;
#pragma unroll
        for (int r = 0; r < TO; r++) {
            float e = __expf(myLog[r * 4 + l] - m);
            s += e;
            myLog[r * 4 + l] = e;
        }
        float inv = 1.f / s;
#pragma unroll
        for (int r = 0; r < TO; r++) myLog[r * 4 + l] *= inv;
    }
    __syncwarp();

    // ubar[g] = sum_r p[r][g] * u_r
    float ub0[4] = {0.f, 0.f, 0.f, 0.f}, ub1[4] = {0.f, 0.f, 0.f, 0.f};
#pragma unroll
    for (int r = 0; r < TO; r++) {
        float pg0 = myLog[r * 4 + 0], pg1 = myLog[r * 4 + 1];
        float pg2 = myLog[r * 4 + 2], pg3 = myLog[r * 4 + 3];
        ub0[0] += pg0 * ur0[r]; ub1[0] += pg0 * ur1[r];
        ub0[1] += pg1 * ur0[r]; ub1[1] += pg1 * ur1[r];
        ub0[2] += pg2 * ur0[r]; ub1[2] += pg2 * ur1[r];
        ub0[3] += pg3 * ur0[r]; ub1[3] += pg3 * ur1[r];
    }

    // attv[oc] = ubar[oc/16] @ Wv[:,oc] + bv[oc]
    float av0 = sbv[l], av1 = sbv[l + 32];
    const bool hi = (l & 16);
#pragma unroll
    for (int in = 0; in < 32; in++) {
        float a0 = __shfl_sync(FULLMASK, ub0[0], in);
        float a1 = __shfl_sync(FULLMASK, ub0[1], in);
        float a2 = __shfl_sync(FULLMASK, ub0[2], in);
        float a3 = __shfl_sync(FULLMASK, ub0[3], in);
        av0 += (hi ? a1 : a0) * sWv[in * 64 + l];
        av1 += (hi ? a3 : a2) * sWv[in * 64 + l + 32];
    }
#pragma unroll
    for (int in = 0; in < 32; in++) {
        float a0 = __shfl_sync(FULLMASK, ub1[0], in);
        float a1 = __shfl_sync(FULLMASK, ub1[1], in);
        float a2 = __shfl_sync(FULLMASK, ub1[2], in);
        float a3 = __shfl_sync(FULLMASK, ub1[3], in);
        av0 += (hi ? a1 : a0) * sWv[(in + 32) * 64 + l];
        av1 += (hi ? a3 : a2) * sWv[(in + 32) * 64 + l + 32];
    }

    // LN1 and write to scratch
    float mean = warp_sum(av0 + av1) * (1.f / 64.f);
    float d0 = av0 - mean, d1 = av1 - mean;
    float var = warp_sum(d0 * d0 + d1 * d1) * (1.f / 64.f);
    float inv = rsqrtf(var + 1e-5f);
    size_t o = ((size_t)b * Nn + n) * Cc;
    g_z1[o + l]      = d0 * inv * sg1[l]      + sbe1[l];
    g_z1[o + l + 32] = d1 * inv * sg1[l + 32] + sbe1[l + 32];
}

extern "C" __global__ void __launch_bounds__(256)
kernelA(const float* __restrict__ u, const float* __restrict__ x,
        const float* __restrict__ Wk, const float* __restrict__ bk,
        const float* __restrict__ Wq, const float* __restrict__ bq,
        const float* __restrict__ Wv, const float* __restrict__ bv,
        const float* __restrict__ g1, const float* __restrict__ be1)
{
    extern __shared__ float sm[];
    float* sWq  = sm;                 // 4096
    float* sWkT = sm + 4096;          // 64*65 = 4160 (pitch 65, conflict-free)
    float* sWv  = sm + 4096 + 4160;   // 4096
    float* sbq  = sWv + 4096;         // 64
    float* sbk  = sbq + 64;
    float* sbv  = sbk + 64;
    float* sg1  = sbv + 64;
    float* sbe1 = sg1 + 64;
    float* sLog = sbe1 + 64;          // 8 warps * 64

    int tid = threadIdx.x;
    for (int i = tid; i < 4096; i += 256) {
        sWq[i] = Wq[i];
        sWv[i] = Wv[i];
        int in = i >> 6, oc = i & 63;
        sWkT[oc * 65 + in] = Wk[i];
    }
    if (tid < 64) {
        sbq[tid] = bq[tid]; sbk[tid] = bk[tid]; sbv[tid] = bv[tid];
        sg1[tid] = g1[tid]; sbe1[tid] = be1[tid];
    }
    __syncthreads();

    int warp = tid >> 5, l = tid & 31;
    float* myLog = sLog + warp * 64;

    for (int blk = blockIdx.x; blk < (Bb * Nn / 8); blk += gridDim.x) {
        int token = blk * 8 + warp;
        int b = token / Nn, n = token % Nn;
        int n0 = (blk % (Nn / 8)) * 8;
        if (n0 < 4096)
            attn_body<4>(u, x, sWq, sWkT, sWv, sbq, sbk, sbv, sg1, sbe1, myLog, b, n, l);
        else if (n0 < 6144)
            attn_body<8>(u, x, sWq, sWkT, sWv, sbq, sbk, sbv, sg1, sbe1, myLog, b, n, l);
        else
            attn_body<16>(u, x, sWq, sWkT, sWv, sbq, sbk, sbv, sg1, sbe1, myLog, b, n, l);
    }
}

// ---------------------------------------------------------------------------
// Kernel B: MLP (64->256 gelu ->64) + LN2 + shortcut (x@Ws+bs)
// ---------------------------------------------------------------------------
extern "C" __global__ void __launch_bounds__(256)
kernelB(const float* __restrict__ x,
        const float* __restrict__ Wm1, const float* __restrict__ bm1,
        const float* __restrict__ Wm2, const float* __restrict__ bm2,
        const float* __restrict__ g2,  const float* __restrict__ be2,
        const float* __restrict__ Ws,  const float* __restrict__ bs,
        float* __restrict__ out)
{
    extern __shared__ float sm[];
    float* sWm1 = sm;               // 16384
    float* sWm2 = sm + 16384;       // 16384
    float* sWs  = sm + 32768;       // 4096
    float* sbm1 = sm + 36864;       // 256
    float* sbm2 = sbm1 + 256;       // 64
    float* sg2  = sbm2 + 64;
    float* sbe2 = sg2 + 64;
    float* sbs  = sbe2 + 64;
    float* sZ   = sbs + 64;         // 32*64
    float* sX   = sZ + 2048;        // 32*64
    float* sH   = sX + 2048;        // 32*256

    int tid = threadIdx.x;
    for (int i = tid; i < 16384; i += 256) { sWm1[i] = Wm1[i]; sWm2[i] = Wm2[i]; }
    for (int i = tid; i < 4096; i += 256) sWs[i] = Ws[i];
    sbm1[tid] = bm1[tid];
    if (tid < 64) { sbm2[tid] = bm2[tid]; sg2[tid] = g2[tid]; sbe2[tid] = be2[tid]; sbs[tid] = bs[tid]; }
    __syncthreads();

    int warp = tid >> 5, l = tid & 31;
    int jb = tid & 63, tg = tid >> 6;   // 4 token-groups of 8, 64 hidden-cols each
    const int NTILES = Bb * Nn / 32;    // 1792

    for (int tile = blockIdx.x; tile < NTILES; tile += gridDim.x) {
        size_t base = (size_t)tile * 32 * 64;
        for (int i = tid; i < 2048; i += 256) {
            sZ[i] = g_z1[base + i];
            sX[i] = x[base + i];
        }
        __syncthreads();

        // MLP1: h[t][j] = gelu(z_t @ Wm1 + bm1); 8 tokens x 4 cols per thread
        float h[8][4];
#pragma unroll
        for (int tt = 0; tt < 8; tt++)
#pragma unroll
            for (int k = 0; k < 4; k++) h[tt][k] = sbm1[jb + 64 * k];

#pragma unroll 4
        for (int c = 0; c < 64; c++) {
            float zr[8];
#pragma unroll
            for (int tt = 0; tt < 8; tt++) zr[tt] = sZ[(tg * 8 + tt) * 64 + c];
            float wr[4];
#pragma unroll
            for (int k = 0; k < 4; k++) wr[k] = sWm1[c * 256 + jb + 64 * k];
#pragma unroll
            for (int tt = 0; tt < 8; tt++)
#pragma unroll
                for (int k = 0; k < 4; k++) h[tt][k] += zr[tt] * wr[k];
        }
#pragma unroll
        for (int tt = 0; tt < 8; tt++)
#pragma unroll
            for (int k = 0; k < 4; k++) {
                float v = h[tt][k];
                h[tt][k] = v * 0.5f * (1.f + erff(v * 0.70710678118654752f));
                sH[(tg * 8 + tt) * 256 + jb + 64 * k] = h[tt][k];
            }
        __syncthreads();

        // MLP2 + shortcut; warp handles 4 tokens, lane -> channels l, l+32
        float o[4][2], sc[4][2];
#pragma unroll
        for (int tt = 0; tt < 4; tt++) {
            o[tt][0] = sbm2[l];  o[tt][1] = sbm2[l + 32];
            sc[tt][0] = sbs[l];  sc[tt][1] = sbs[l + 32];
        }
#pragma unroll 4
        for (int j = 0; j < 256; j++) {
            float w2a = sWm2[j * 64 + l], w2b = sWm2[j * 64 + l + 32];
#pragma unroll
            for (int tt = 0; tt < 4; tt++) {
                float hb = sH[(warp * 4 + tt) * 256 + j];
                o[tt][0] += hb * w2a;
                o[tt][1] += hb * w2b;
            }
        }
#pragma unroll 4
        for (int in = 0; in < 64; in++) {
            float wsa = sWs[in * 64 + l], wsb = sWs[in * 64 + l + 32];
#pragma unroll
            for (int tt = 0; tt < 4; tt++) {
                float xb = sX[(warp * 4 + tt) * 64 + in];
                sc[tt][0] += xb * wsa;
                sc[tt][1] += xb * wsb;
            }
        }
#pragma unroll
        for (int tt = 0; tt < 4; tt++) {
            float mean = warp_sum(o[tt][0] + o[tt][1]) * (1.f / 64.f);
            float d0 = o[tt][0] - mean, d1 = o[tt][1] - mean;
            float var = warp_sum(d0 * d0 + d1 * d1) * (1.f / 64.f);
            float inv = rsqrtf(var + 1e-5f);
            size_t oo = base + (size_t)(warp * 4 + tt) * 64;
            out[oo + l]      = d0 * inv * sg2[l]      + sbe2[l]      + sc[tt][0];
            out[oo + l + 32] = d1 * inv * sg2[l + 32] + sbe2[l + 32] + sc[tt][1];
        }
        __syncthreads();
    }
}

// ---------------------------------------------------------------------------
extern "C" void kernel_launch(void* const* d_in, const int* in_sizes, int n_in,
                              void* d_out, int out_size)
{
    const float* u   = (const float*)d_in[0];
    const float* x   = (const float*)d_in[1];
    const float* Wk  = (const float*)d_in[2];
    const float* bk  = (const float*)d_in[3];
    const float* Wq  = (const float*)d_in[4];
    const float* bq  = (const float*)d_in[5];
    const float* Wv  = (const float*)d_in[6];
    const float* bv  = (const float*)d_in[7];
    const float* g1  = (const float*)d_in[8];
    const float* be1 = (const float*)d_in[9];
    const float* Wm1 = (const float*)d_in[10];
    const float* bm1 = (const float*)d_in[11];
    const float* Wm2 = (const float*)d_in[12];
    const float* bm2 = (const float*)d_in[13];
    const float* g2  = (const float*)d_in[14];
    const float* be2 = (const float*)d_in[15];
    const float* Ws  = (const float*)d_in[16];
    const float* bs  = (const float*)d_in[17];
    float* out = (float*)d_out;

    const int smemA = (4096 + 4160 + 4096 + 5 * 64 + 8 * 64) * 4;   // 52800 B
    const int smemB = (16384 + 16384 + 4096 + 256 + 4 * 64 + 2048 + 2048 + 8192) * 4; // 198656 B

    cudaFuncSetAttribute(kernelA, cudaFuncAttributeMaxDynamicSharedMemorySize, smemA);
    cudaFuncSetAttribute(kernelB, cudaFuncAttributeMaxDynamicSharedMemorySize, smemB);

    kernelA<<<444, 256, smemA>>>(u, x, Wk, bk, Wq, bq, Wv, bv, g1, be1);
    kernelB<<<148, 256, smemB>>>(x, Wm1, bm1, Wm2, bm2, g2, be2, Ws, bs, out);
}